// round 5
// baseline (speedup 1.0000x reference)
#include <cuda_runtime.h>

#define NFEAT 256
#define QBANK 2048
#define DDIM  512
#define CCLS  1000
#define IMGE  150528           // 3*224*224
#define IMG4  (IMGE/4)         // 37632
#define KNN   4
#define NJBLK (QBANK / 64)     // 32

// Scratch (allocation-free rule: __device__ globals)
__device__ unsigned long long g_cand[NFEAT * NJBLK * 4]; // per-row per-jblk top4 keys

__device__ __forceinline__ unsigned sortable_f32(float v) {
    unsigned u = __float_as_uint(v);
    return (u & 0x80000000u) ? ~u : (u | 0x80000000u);
}
__device__ __forceinline__ void ffma2(unsigned long long& acc,
                                      unsigned long long a,
                                      unsigned long long b) {
    asm("fma.rn.f32x2 %0, %1, %2, %0;" : "+l"(acc) : "l"(a), "l"(b));
}
__device__ __forceinline__ unsigned long long pk2(float lo, float hi) {
    unsigned long long r;
    asm("mov.b64 %0, {%1, %2};" : "=l"(r) : "f"(lo), "f"(hi));
    return r;
}
__device__ __forceinline__ float2 unpk2(unsigned long long v) {
    float lo, hi;
    asm("mov.b64 {%0, %1}, %2;" : "=f"(lo), "=f"(hi) : "l"(v));
    return make_float2(lo, hi);
}
__device__ __forceinline__ void ins4(unsigned long long v, unsigned long long b[4]) {
    if (v < b[3]) {
        b[3] = v;
        if (b[3] < b[2]) { unsigned long long t = b[2]; b[2] = b[3]; b[3] = t; }
        if (b[2] < b[1]) { unsigned long long t = b[1]; b[1] = b[2]; b[2] = t; }
        if (b[1] < b[0]) { unsigned long long t = b[0]; b[0] = b[1]; b[1] = t; }
    }
}

// ---------------------------------------------------------------------------
// K1: GEMM (FFMA2) + fused norms + fused local top-4 epilogue.
// 32i x 64j tile, 128 threads, 4i x 4j microtile.
// - column norms computed per block from L2-hot B rows
// - A/B transposed into smem during the load phase (no prep kernel)
// - epilogue: per row merge 16 lanes' 4-candidate lists -> g_cand
// ---------------------------------------------------------------------------
__global__ void __launch_bounds__(128) k_sim(const float* __restrict__ A,
                                             const float* __restrict__ B) {
    __shared__ float2 As2[32][34];      // [k][i] dup pairs (padded)
    __shared__ float  Bs[32][68];       // [k][j] (padded)
    __shared__ float  binv_s[64];

    int tid = threadIdx.x;
    int tx = tid & 15;
    int ty = tid >> 4;
    int i0 = blockIdx.y * 32;
    int j0 = blockIdx.x * 64;

    // ---- fused column norms: 2 threads per j-row ----
    {
        int r = tid >> 1, h = tid & 1;
        const float4* row = reinterpret_cast<const float4*>(B + (size_t)(j0 + r) * DDIM);
        float s = 0.f;
        #pragma unroll 8
        for (int t = 0; t < 64; t++) {
            float4 v = row[h * 64 + t];
            s += v.x * v.x + v.y * v.y + v.z * v.z + v.w * v.w;
        }
        s += __shfl_down_sync(0xffffffffu, s, 1);
        if (h == 0) binv_s[r] = 1.0f / sqrtf(fmaxf(s, 1e-24f));
    }

    unsigned long long acc[4][2];
    #pragma unroll
    for (int x = 0; x < 4; x++)
        #pragma unroll
        for (int y = 0; y < 2; y++) acc[x][y] = pk2(0.f, 0.f);

    #pragma unroll 1
    for (int k0 = 0; k0 < DDIM; k0 += 32) {
        // A tile: 32i x 32k, transpose + duplicate into As2[k][i]
        #pragma unroll
        for (int q = 0; q < 2; q++) {
            int lin = q * 128 + tid;
            int ir = lin >> 3, k4 = lin & 7;
            float4 v = *reinterpret_cast<const float4*>(
                A + (size_t)(i0 + ir) * DDIM + k0 + k4 * 4);
            As2[k4 * 4 + 0][ir] = make_float2(v.x, v.x);
            As2[k4 * 4 + 1][ir] = make_float2(v.y, v.y);
            As2[k4 * 4 + 2][ir] = make_float2(v.z, v.z);
            As2[k4 * 4 + 3][ir] = make_float2(v.w, v.w);
        }
        // B tile: 64j x 32k, transpose into Bs[k][j]
        #pragma unroll
        for (int q = 0; q < 4; q++) {
            int lin = q * 128 + tid;
            int jr = lin >> 3, k4 = lin & 7;
            float4 v = *reinterpret_cast<const float4*>(
                B + (size_t)(j0 + jr) * DDIM + k0 + k4 * 4);
            Bs[k4 * 4 + 0][jr] = v.x;
            Bs[k4 * 4 + 1][jr] = v.y;
            Bs[k4 * 4 + 2][jr] = v.z;
            Bs[k4 * 4 + 3][jr] = v.w;
        }
        __syncthreads();
        #pragma unroll
        for (int kk = 0; kk < 32; kk++) {
            float4 a01 = *reinterpret_cast<const float4*>(&As2[kk][ty * 4]);
            float4 a23 = *reinterpret_cast<const float4*>(&As2[kk][ty * 4 + 2]);
            float4 bv  = *reinterpret_cast<const float4*>(&Bs[kk][tx * 4]);
            unsigned long long b01 = pk2(bv.x, bv.y);
            unsigned long long b23 = pk2(bv.z, bv.w);
            unsigned long long a0 = pk2(a01.x, a01.y);
            unsigned long long a1 = pk2(a01.z, a01.w);
            unsigned long long a2 = pk2(a23.x, a23.y);
            unsigned long long a3 = pk2(a23.z, a23.w);
            ffma2(acc[0][0], a0, b01); ffma2(acc[0][1], a0, b23);
            ffma2(acc[1][0], a1, b01); ffma2(acc[1][1], a1, b23);
            ffma2(acc[2][0], a2, b01); ffma2(acc[2][1], a2, b23);
            ffma2(acc[3][0], a3, b01); ffma2(acc[3][1], a3, b23);
        }
        __syncthreads();
    }

    // ---- fused local top-4 per row ----
    float bv0 = binv_s[tx * 4 + 0];
    float bv1 = binv_s[tx * 4 + 1];
    float bv2 = binv_s[tx * 4 + 2];
    float bv3 = binv_s[tx * 4 + 3];
    unsigned jbase = (unsigned)(j0 + tx * 4);
    #pragma unroll
    for (int x = 0; x < 4; x++) {
        float2 v01 = unpk2(acc[x][0]);
        float2 v23 = unpk2(acc[x][1]);
        unsigned long long b[4] = {~0ull, ~0ull, ~0ull, ~0ull};
        ins4(((unsigned long long)sortable_f32(v01.x * bv0) << 32) | (jbase + 0), b);
        ins4(((unsigned long long)sortable_f32(v01.y * bv1) << 32) | (jbase + 1), b);
        ins4(((unsigned long long)sortable_f32(v23.x * bv2) << 32) | (jbase + 2), b);
        ins4(((unsigned long long)sortable_f32(v23.y * bv3) << 32) | (jbase + 3), b);
        #pragma unroll
        for (int o = 8; o > 0; o >>= 1) {
            unsigned long long ov[4];
            #pragma unroll
            for (int t = 0; t < 4; t++) ov[t] = __shfl_down_sync(0xffffffffu, b[t], o);
            #pragma unroll
            for (int t = 0; t < 4; t++) ins4(ov[t], b);
        }
        if (tx == 0) {
            int i = i0 + ty * 4 + x;
            unsigned long long* dst = &g_cand[((size_t)i * NJBLK + blockIdx.x) * 4];
            #pragma unroll
            for (int t = 0; t < 4; t++) dst[t] = b[t];
        }
    }
}

// ---------------------------------------------------------------------------
// K2: fused gather (images + grads + probs + labels).
// Each block first merges row i's 128 candidate keys (redundant but cheap,
// g_cand is L2-resident) -> no separate topk kernel, no g_idx round trip.
// ---------------------------------------------------------------------------
__global__ void k_gather(const float* __restrict__ img,
                         const float* __restrict__ bank,
                         const float* __restrict__ probs,
                         float* __restrict__ out_images,
                         float* __restrict__ out_grads,
                         float* __restrict__ out_probs,
                         float* __restrict__ out_labels) {
    int i = blockIdx.x;
    int wid = threadIdx.x >> 5, lid = threadIdx.x & 31;

    __shared__ int idx_s[4];
    if (wid == 0) {
        const unsigned long long* cand = &g_cand[(size_t)i * NJBLK * 4];
        unsigned long long b[4] = {~0ull, ~0ull, ~0ull, ~0ull};
        ins4(cand[lid], b);
        ins4(cand[lid + 32], b);
        ins4(cand[lid + 64], b);
        ins4(cand[lid + 96], b);
        #pragma unroll
        for (int o = 16; o > 0; o >>= 1) {
            unsigned long long ov[4];
            #pragma unroll
            for (int t = 0; t < 4; t++) ov[t] = __shfl_down_sync(0xffffffffu, b[t], o);
            #pragma unroll
            for (int t = 0; t < 4; t++) ins4(ov[t], b);
        }
        if (lid == 0) {
            #pragma unroll
            for (int t = 0; t < 4; t++) idx_s[t] = (int)(b[t] & 0xffffffffu);
        }
    }
    __syncthreads();
    int4 id = *reinterpret_cast<const int4*>(idx_s);

    if (blockIdx.y < 49) {
        int base = blockIdx.y * 768 + threadIdx.x;
        const float4* im = reinterpret_cast<const float4*>(img);
        size_t r0 = (size_t)id.x * IMG4, r1 = (size_t)id.y * IMG4;
        size_t r2 = (size_t)id.z * IMG4, r3 = (size_t)id.w * IMG4;
        float4* o = reinterpret_cast<float4*>(out_images) + (size_t)i * IMG4;
        #pragma unroll
        for (int q = 0; q < 3; q++) {
            int e4 = base + q * 256;
            float4 a = im[r0 + e4];
            float4 b = im[r1 + e4];
            float4 c = im[r2 + e4];
            float4 d = im[r3 + e4];
            float4 v;
            v.x = (a.x + b.x + c.x + d.x) * 0.25f;
            v.y = (a.y + b.y + c.y + d.y) * 0.25f;
            v.z = (a.z + b.z + c.z + d.z) * 0.25f;
            v.w = (a.w + b.w + c.w + d.w) * 0.25f;
            __stcs(o + e4, v);
        }
        return;
    }

    // grads_m
    if (threadIdx.x < DDIM / 4) {
        int t = threadIdx.x;
        const float4* r0 = reinterpret_cast<const float4*>(bank + (size_t)id.x * DDIM);
        const float4* r1 = reinterpret_cast<const float4*>(bank + (size_t)id.y * DDIM);
        const float4* r2 = reinterpret_cast<const float4*>(bank + (size_t)id.z * DDIM);
        const float4* r3 = reinterpret_cast<const float4*>(bank + (size_t)id.w * DDIM);
        float4 a = r0[t], b = r1[t], c = r2[t], d = r3[t];
        float4 v;
        v.x = (a.x + b.x + c.x + d.x) * 0.25f;
        v.y = (a.y + b.y + c.y + d.y) * 0.25f;
        v.z = (a.z + b.z + c.z + d.z) * 0.25f;
        v.w = (a.w + b.w + c.w + d.w) * 0.25f;
        reinterpret_cast<float4*>(out_grads + (size_t)i * DDIM)[t] = v;
    }

    // pred_probs + argmax
    const float* p0 = probs + (size_t)id.x * CCLS;
    const float* p1 = probs + (size_t)id.y * CCLS;
    const float* p2 = probs + (size_t)id.z * CCLS;
    const float* p3 = probs + (size_t)id.w * CCLS;
    unsigned long long best = 0ull;
    for (int c = threadIdx.x; c < CCLS; c += blockDim.x) {
        float p = (p0[c] + p1[c] + p2[c] + p3[c]) * 0.25f;
        out_probs[(size_t)i * CCLS + c] = p;
        unsigned long long key =
            ((unsigned long long)sortable_f32(p) << 32) | (0xFFFFFFFFu - (unsigned)c);
        best = max(best, key);
    }
    #pragma unroll
    for (int o = 16; o > 0; o >>= 1)
        best = max(best, __shfl_down_sync(0xffffffffu, best, o));
    __shared__ unsigned long long red[8];
    if (lid == 0) red[wid] = best;
    __syncthreads();
    if (threadIdx.x == 0) {
        unsigned long long m = red[0];
        #pragma unroll
        for (int w = 1; w < 8; w++) m = max(m, red[w]);
        unsigned c = 0xFFFFFFFFu - (unsigned)(m & 0xffffffffu);
        out_labels[i] = (float)c;
    }
}

// ---------------------------------------------------------------------------
extern "C" void kernel_launch(void* const* d_in, const int* in_sizes, int n_in,
                              void* d_out, int out_size) {
    const float* features = (const float*)d_in[0];   // (256,512)
    const float* bank     = (const float*)d_in[1];   // (2048,512)
    const float* probs    = (const float*)d_in[2];   // (2048,1000)
    const float* images   = (const float*)d_in[3];   // (2048,3,224,224)
    (void)in_sizes; (void)n_in; (void)out_size;

    float* out        = (float*)d_out;
    float* out_labels = out;                                   // 256
    float* out_probs  = out + NFEAT;                           // 256*1000
    float* out_images = out_probs + (size_t)NFEAT * CCLS;      // 256*150528
    float* out_grads  = out_images + (size_t)NFEAT * IMGE;     // 256*512

    k_sim<<<dim3(NJBLK, NFEAT / 32), 128>>>(features, bank);
    k_gather<<<dim3(NFEAT, 49 + 1), 256>>>(
        images, bank, probs, out_images, out_grads, out_probs, out_labels);
}